// round 2
// baseline (speedup 1.0000x reference)
#include <cuda_runtime.h>
#include <cstdint>

// Problem constants
constexpr int B = 16384;
constexpr int F = 50;
constexpr int K = 64;
constexpr int ROWS_PER_BLOCK = 4;   // 4 rows x 64 threads = 256 threads

__global__ __launch_bounds__(ROWS_PER_BLOCK * K)
void fm_second_order_kernel(const float* __restrict__ vals,  // [B, F]
                            const int*   __restrict__ idx,   // [B, F] int32
                            const float* __restrict__ emb,   // [FEATURE_SIZE, K]
                            float* __restrict__ out)         // [B, K]
{
    const int row_in_blk = threadIdx.x >> 6;     // 0..3
    const int k          = threadIdx.x & (K - 1);
    const int row        = blockIdx.x * ROWS_PER_BLOCK + row_in_blk;

    __shared__ float sv[ROWS_PER_BLOCK][F];
    __shared__ int   soff[ROWS_PER_BLOCK][F];    // element offset = idx * K (fits int32)

    // Each 64-thread group stages its own row's idx/values (threads 0..49 of group)
    if (k < F) {
        sv[row_in_blk][k]   = vals[row * F + k];
        soff[row_in_blk][k] = idx[row * F + k] * K;
    }
    __syncthreads();

    float s1 = 0.0f;
    float s2 = 0.0f;

#pragma unroll
    for (int f = 0; f < F; ++f) {
        const float v = sv[row_in_blk][f];
        const float e = __ldg(&emb[soff[row_in_blk][f] + k]);
        const float ve = v * e;
        s1 += ve;
        s2 += ve * ve;   // v^2 * e^2
    }

    out[row * K + k] = s1 * s1 - s2;
}

extern "C" void kernel_launch(void* const* d_in, const int* in_sizes, int n_in,
                              void* d_out, int out_size)
{
    const float* vals = (const float*)d_in[0];   // feature_values [B,F] f32
    const int*   idx  = (const int*)d_in[1];     // feature_idx    [B,F] i32
    const float* emb  = (const float*)d_in[2];   // feature_embeddings [1e6,K] f32
    float*       out  = (float*)d_out;           // [B,K] f32

    const int grid = B / ROWS_PER_BLOCK;         // 4096
    fm_second_order_kernel<<<grid, ROWS_PER_BLOCK * K>>>(vals, idx, emb, out);
}

// round 7
// speedup vs baseline: 1.0738x; 1.0738x over previous
#include <cuda_runtime.h>
#include <cstdint>

constexpr int B = 16384;
constexpr int F = 50;
constexpr int K = 64;
constexpr int TPR = 16;              // threads per row: each owns 4 k's (one float4)
constexpr int RPB = 16;              // rows per block: 16 x 16 = 256 threads

__global__ __launch_bounds__(RPB * TPR)
void fm2_kernel(const float* __restrict__ vals,  // [B, F]
                const int*   __restrict__ idx,   // [B, F] int32
                const float* __restrict__ emb,   // [1e6, K] f32
                float* __restrict__ out)         // [B, K] f32
{
    const int tid   = threadIdx.x;
    const int r_blk = tid >> 4;                  // 0..15
    const int kq    = tid & (TPR - 1);           // float4 column 0..15
    const int row   = blockIdx.x * RPB + r_blk;

    __shared__ float sv[RPB][F];
    __shared__ int   soff[RPB][F];               // float4-element offset = idx * 16

    // Stage 16 rows x 50 fields of (value, offset) cooperatively.
    // Block-global flat index; r = i/50 via multiply-shift is compiler's job.
    for (int i = tid; i < RPB * F; i += RPB * TPR) {
        const int r = i / F;
        const int f = i - r * F;
        const int g = (blockIdx.x * RPB + r) * F + f;
        sv[r][f]   = vals[g];
        soff[r][f] = idx[g] * (K / 4);           // index into float4-view of emb
    }
    __syncthreads();

    const float4* __restrict__ emb4 = (const float4*)emb;

    float s1x = 0.f, s1y = 0.f, s1z = 0.f, s1w = 0.f;
    float s2x = 0.f, s2y = 0.f, s2z = 0.f, s2w = 0.f;

#pragma unroll
    for (int f = 0; f < F; ++f) {
        const float  v = sv[r_blk][f];
        const float4 e = __ldg(&emb4[soff[r_blk][f] + kq]);
        const float ax = v * e.x, ay = v * e.y, az = v * e.z, aw = v * e.w;
        s1x += ax;      s1y += ay;      s1z += az;      s1w += aw;
        s2x += ax * ax; s2y += ay * ay; s2z += az * az; s2w += aw * aw;
    }

    float4 o;
    o.x = s1x * s1x - s2x;
    o.y = s1y * s1y - s2y;
    o.z = s1z * s1z - s2z;
    o.w = s1w * s1w - s2w;
    ((float4*)out)[row * TPR + kq] = o;
}

extern "C" void kernel_launch(void* const* d_in, const int* in_sizes, int n_in,
                              void* d_out, int out_size)
{
    const float* vals = (const float*)d_in[0];
    const int*   idx  = (const int*)d_in[1];
    const float* emb  = (const float*)d_in[2];
    float*       out  = (float*)d_out;

    fm2_kernel<<<B / RPB, RPB * TPR>>>(vals, idx, emb, out);
}